// round 11
// baseline (speedup 1.0000x reference)
#include <cuda_runtime.h>
#include <cuda_bf16.h>
#include <math.h>
#include <stdint.h>

// ===================== problem constants =====================
#define NB   16
#define NC   256
#define NHW  1024
#define NTOK (NB * NHW)        // 16384
#define NK   8192
#define NQ   (NB * NC * NHW)   // 4194304

#define DELTA 0.75f
#define CAND_CAP 16

// ===================== device scratch =====================
__device__ __align__(16) uint32_t g_zfrag[(NTOK / 128) * 16384];  // 8MB, frag-order A
__device__ __align__(16) __nv_bfloat16 g_ebf[NK * NC];            // 4MB, bf16(-2e)
__device__ __align__(16) float g_zt[NTOK * NC];                   // 16MB, z transposed [n][c]
__device__ float  g_cbnorm[NK];
__device__ __align__(16) int g_idx[NTOK];
__device__ int    g_counts[NK];
__device__ double g_loss;

__device__ __forceinline__ uint32_t smem_u32(const void* p) {
    uint32_t a;
    asm("{ .reg .u64 t; cvta.to.shared.u64 t, %1; cvt.u32.u64 %0, t; }" : "=r"(a) : "l"(p));
    return a;
}

// ===================== prep z: transpose + staged frag writes + fp32 copy ======
__global__ void vq_prep_z_kernel(const float* __restrict__ z) {
    __shared__ float t[32][33];
    __shared__ uint32_t fr[512];
    int b   = blockIdx.z;
    int hw0 = blockIdx.x * 32;
    int c0  = blockIdx.y * 32;
    int lane = threadIdx.x & 31;
    int gq   = threadIdx.x >> 5;   // 0..7
    const float* zp = z + ((size_t)b * NC + c0) * NHW + hw0;
#pragma unroll
    for (int r = 0; r < 4; r++) {
        int cc = gq * 4 + r;
        t[cc][lane] = zp[(size_t)cc * NHW + lane];
    }
    __syncthreads();
#pragma unroll
    for (int it = 0; it < 2; it++) {
        int slot = threadIdx.x + it * 256;      // 0..511
        int hw_i = slot & 31;
        int cp   = slot >> 5;                   // 0..15
        float v0 = t[2 * cp][hw_i];
        float v1 = t[2 * cp + 1][hw_i];
        uint32_t lo = (uint32_t)__bfloat16_as_ushort(__float2bfloat16(v0));
        uint32_t hi = (uint32_t)__bfloat16_as_ushort(__float2bfloat16(v1));
        uint32_t pk = lo | (hi << 16);

        int kk = (2 * cp) & 15;
        int s  = cp >> 3;                       // ks selector (0/1)
        int u  = hw_i >> 4;                     // mt selector (0/1)
        int g  = hw_i & 7;
        int rl = (hw_i >> 3) & 1;
        int tg = (kk >> 1) & 3;
        int rh = kk >> 3;
        int l  = g * 4 + tg;
        int r  = rl + 2 * rh;
        fr[(s * 2 + u) * 128 + l * 4 + r] = pk;
    }
#pragma unroll
    for (int i = 0; i < 4; i++) {
        int tok_l = gq * 4 + i;
        int n = b * NHW + hw0 + tok_l;
        g_zt[(size_t)n * NC + c0 + lane] = t[lane][tok_l];
    }
    __syncthreads();
    if (threadIdx.x < 128) {
        int q = threadIdx.x;
        int s = q >> 6, u = (q >> 5) & 1, off = q & 31;
        int n0  = b * NHW + hw0;
        int blk = n0 >> 7;
        int mt0 = (n0 & 127) >> 4;
        int ks0 = c0 >> 4;
        uint4* dst4 = (uint4*)g_zfrag;
        const uint4* fr4 = (const uint4*)fr;
        dst4[(size_t)((blk * 16 + ks0 + s) * 8 + (mt0 + u)) * 32 + off] = fr4[q];
    }
}

// ===================== fused prep: cbnorm + bf16(-2e) + init =====================
__global__ void vq_prep_cb_kernel(const float* __restrict__ cb) {
    int row  = blockIdx.x * 8 + (threadIdx.x >> 5);
    int lane = threadIdx.x & 31;
    const float* rp = cb + (size_t)row * NC;
    float v[8];
    float s = 0.f;
#pragma unroll
    for (int i = 0; i < 8; i++) {
        v[i] = rp[lane + i * 32];
        s += v[i] * v[i];
    }
#pragma unroll
    for (int off = 16; off; off >>= 1) s += __shfl_down_sync(0xffffffffu, s, off);
    if (lane == 0) g_cbnorm[row] = s;
#pragma unroll
    for (int i = 0; i < 8; i++)
        g_ebf[(size_t)row * NC + lane + i * 32] = __float2bfloat16(-2.0f * v[i]);
    int gid = blockIdx.x * 256 + threadIdx.x;
    if (gid < NK) g_counts[gid] = 0;
    if (gid == 0) g_loss = 0.0;
}

// ===================== main kernel: R7 body + fused exact rescore tail ==========
// warp (wm 0..3, wn 0..3): M rows [wm*32,+32), N cols [wn*32,+32)
// SMEM layout (bytes):
//   [0, 65536)         A frags (u32[16][8][32][4])
//   [65536, 102400)    B double buffer: 2 x 128 rows x 144B
//   [102400, 135168)   cbnorm (8192 f32)
//   [135168, 137216)   snc[16][32]
//   [137216, 169984)   scand[16][32][16]
#define SM_A     0
#define SM_B     65536
#define SM_BSTG  18432
#define BROW_STRIDE 144
#define SM_CBN   102400
#define SM_SNC   135168
#define SM_SCAND 137216
#define SM_TOTAL 169984

__global__ void __launch_bounds__(512, 1) vq_argmin_mma_kernel(const float* __restrict__ cb) {
    extern __shared__ char smem[];
    uint32_t sb = smem_u32(smem);
    const int tid  = threadIdx.x;
    const int wid  = tid >> 5;
    const int lane = tid & 31;
    const int wm   = wid >> 2;       // 0..3
    const int wn   = wid & 3;        // 0..3
    const int g    = lane >> 2;      // 0..7
    const int tg   = lane & 3;       // 0..3
    const int blk  = blockIdx.x;
    const int n_base = blk * 128;

    uint4*  Asm   = (uint4*)(smem + SM_A);
    float*  cbn   = (float*)(smem + SM_CBN);
    int*    snc   = (int*)(smem + SM_SNC);          // [16][32]
    int*    scand = (int*)(smem + SM_SCAND);        // [16][32][16]

    // ---- stage A frags + cbnorm, zero counters ----
    {
        const uint4* src = (const uint4*)(g_zfrag + (size_t)blk * 16384);
#pragma unroll
        for (int i = 0; i < 8; i++) Asm[tid + i * 512] = src[tid + i * 512];
        const float4* cs = (const float4*)g_cbnorm;
        float4* cd = (float4*)cbn;
#pragma unroll
        for (int i = 0; i < 4; i++) cd[tid + i * 512] = cs[tid + i * 512];
        snc[tid] = 0;
    }
    __syncthreads();

    // ---- cp.async B loader: per chunk 128 rows x 128B; thread -> (row, 32B quarter) ----
    const int brow = tid >> 2;        // 0..127
    const int bq   = tid & 3;         // 32B quarter
    {
        const char* src = (const char*)(g_ebf) + (size_t)brow * 512 + bq * 32;
        uint32_t dst = sb + SM_B + brow * BROW_STRIDE + bq * 32;
        asm volatile("cp.async.cg.shared.global [%0], [%1], 16;" :: "r"(dst), "l"(src));
        asm volatile("cp.async.cg.shared.global [%0], [%1], 16;" :: "r"(dst + 16), "l"(src + 16));
        asm volatile("cp.async.commit_group;" ::: "memory");
    }

    float acc[2][4][4];
    float minv[4];
#pragma unroll
    for (int i = 0; i < 4; i++) minv[i] = 3.4e38f;

    const int rowsel = lane >> 4;
    const int kbsel  = ((lane >> 3) & 1) * 16;
    const uint32_t bA1 = (uint32_t)(((wn * 4 + rowsel) * 8 + (lane & 7)) * BROW_STRIDE + kbsel);
    const uint32_t bA2 = (uint32_t)(((wn * 4 + 2 + rowsel) * 8 + (lane & 7)) * BROW_STRIDE + kbsel);

    for (int T = 0; T < 256; T++) {
        const int tile = T >> 2;
        const int q2   = T & 3;

        asm volatile("cp.async.wait_group 0;" ::: "memory");
        __syncthreads();

        if (T + 1 < 256) {
            const int Tn = T + 1;
            const char* src = (const char*)(g_ebf) +
                (size_t)((Tn >> 2) * 128 + brow) * 512 + (Tn & 3) * 128 + bq * 32;
            uint32_t dst = sb + SM_B + ((Tn & 1) * SM_BSTG) + brow * BROW_STRIDE + bq * 32;
            asm volatile("cp.async.cg.shared.global [%0], [%1], 16;" :: "r"(dst), "l"(src));
            asm volatile("cp.async.cg.shared.global [%0], [%1], 16;" :: "r"(dst + 16), "l"(src + 16));
            asm volatile("cp.async.commit_group;" ::: "memory");
        }

        if (q2 == 0) {
#pragma unroll
            for (int m = 0; m < 2; m++)
#pragma unroll
                for (int j = 0; j < 4; j++)
#pragma unroll
                    for (int r = 0; r < 4; r++) acc[m][j][r] = 0.f;
        }

        const uint32_t bbase = sb + SM_B + (T & 1) * SM_BSTG;
#pragma unroll
        for (int s2 = 0; s2 < 4; s2++) {
            const int ks = q2 * 4 + s2;
            uint32_t a[2][4];
#pragma unroll
            for (int m2 = 0; m2 < 2; m2++) {
                uint4 v = Asm[(ks * 8 + (wm * 2 + m2)) * 32 + lane];
                a[m2][0] = v.x; a[m2][1] = v.y; a[m2][2] = v.z; a[m2][3] = v.w;
            }
            uint32_t b[4][2];
            asm volatile("ldmatrix.sync.aligned.m8n8.x4.shared.b16 {%0,%1,%2,%3}, [%4];"
                : "=r"(b[0][0]), "=r"(b[0][1]), "=r"(b[1][0]), "=r"(b[1][1])
                : "r"(bbase + bA1 + s2 * 32));
            asm volatile("ldmatrix.sync.aligned.m8n8.x4.shared.b16 {%0,%1,%2,%3}, [%4];"
                : "=r"(b[2][0]), "=r"(b[2][1]), "=r"(b[3][0]), "=r"(b[3][1])
                : "r"(bbase + bA2 + s2 * 32));
#pragma unroll
            for (int m2 = 0; m2 < 2; m2++)
#pragma unroll
                for (int j = 0; j < 4; j++) {
                    asm volatile(
                        "mma.sync.aligned.m16n8k16.row.col.f32.bf16.bf16.f32 "
                        "{%0,%1,%2,%3}, {%4,%5,%6,%7}, {%8,%9}, {%0,%1,%2,%3};"
                        : "+f"(acc[m2][j][0]), "+f"(acc[m2][j][1]),
                          "+f"(acc[m2][j][2]), "+f"(acc[m2][j][3])
                        : "r"(a[m2][0]), "r"(a[m2][1]), "r"(a[m2][2]), "r"(a[m2][3]),
                          "r"(b[j][0]), "r"(b[j][1]));
                }
        }

        if (q2 == 3) {
            const int nb = tile * 128 + wn * 32;
            float2 cb2[4];
#pragma unroll
            for (int j = 0; j < 4; j++)
                cb2[j] = *(const float2*)(cbn + nb + j * 8 + 2 * tg);
#pragma unroll
            for (int mh = 0; mh < 4; mh++) {
                const int m = mh >> 1, h = mh & 1;
                float d0[8];
#pragma unroll
                for (int j = 0; j < 4; j++) {
                    d0[2 * j]     = acc[m][j][2 * h]     + cb2[j].x;
                    d0[2 * j + 1] = acc[m][j][2 * h + 1] + cb2[j].y;
                }
                float lm = d0[0];
#pragma unroll
                for (int i = 1; i < 8; i++) lm = fminf(lm, d0[i]);
                lm = fminf(lm, __shfl_xor_sync(0xffffffffu, lm, 1));
                lm = fminf(lm, __shfl_xor_sync(0xffffffffu, lm, 2));
                if (lm < minv[mh] + DELTA) {
                    const float thr2 = fminf(minv[mh], lm) + DELTA;
                    const int tl = m * 16 + h * 8 + g;
#pragma unroll
                    for (int j = 0; j < 4; j++)
#pragma unroll
                        for (int p = 0; p < 2; p++) {
                            float d = d0[2 * j + p];
                            if (d < thr2) {
                                int slot = atomicAdd(&snc[wid * 32 + tl], 1);
                                if (slot < CAND_CAP)
                                    scand[(wid * 32 + tl) * CAND_CAP + slot] =
                                        nb + j * 8 + 2 * tg + p;
                            }
                        }
                    minv[mh] = fminf(minv[mh], lm);
                }
            }
        }
    }

    __syncthreads();

    // ======== fused merge + EXACT rescore: warp wid handles tokens wid*8..+7 ========
    for (int t8 = 0; t8 < 8; t8++) {
        const int t   = wid * 8 + t8;       // local token 0..127
        const int wmg = t >> 5, tl = t & 31;
        const int tok = n_base + t;

        const float* zp = g_zt + (size_t)tok * NC;
        float zr[8];
#pragma unroll
        for (int u = 0; u < 8; u++) zr[u] = zp[lane + u * 32];

        float bd = 3.4e38f;
        int bk = 0x7fffffff;
        bool ovf = false;
#pragma unroll
        for (int j = 0; j < 4; j++) {
            const int w2 = wmg * 4 + j;
            int cnum = snc[w2 * 32 + tl];
            if (cnum > CAND_CAP) { ovf = true; cnum = CAND_CAP; }
            for (int s = 0; s < cnum; s++) {
                const int k = scand[(w2 * 32 + tl) * CAND_CAP + s];
                const float* cr = cb + (size_t)k * NC + lane;
                float sum = 0.f;
#pragma unroll
                for (int u = 0; u < 8; u++) sum += zr[u] * cr[u * 32];
#pragma unroll
                for (int off = 16; off; off >>= 1)
                    sum += __shfl_xor_sync(0xffffffffu, sum, off);
                float d = cbn[k] - 2.0f * sum;
                if (d < bd || (d == bd && k < bk)) { bd = d; bk = k; }
            }
        }
        if (ovf) {
            for (int k = 0; k < NK; k++) {
                const float* cr = cb + (size_t)k * NC + lane;
                float sum = 0.f;
#pragma unroll
                for (int u = 0; u < 8; u++) sum += zr[u] * cr[u * 32];
#pragma unroll
                for (int off = 16; off; off >>= 1)
                    sum += __shfl_xor_sync(0xffffffffu, sum, off);
                float d = cbn[k] - 2.0f * sum;
                if (d < bd || (d == bd && k < bk)) { bd = d; bk = k; }
            }
        }
        if (lane == 0) g_idx[tok] = bk;
    }
}

// ===================== writeback =====================
__global__ void vq_writeback_kernel(const float* __restrict__ z, const float* __restrict__ cb,
                                    float* __restrict__ out) {
    const int tid = threadIdx.x;
    const int gid = blockIdx.x * 256 + tid;
    const int hw  = gid & 1023;
    const int cq  = (gid >> 10) & 63;
    const int b   = gid >> 16;
    const int n   = (b << 10) | hw;
    const int c   = cq * 4;

    const int k = g_idx[n];
    float4 q = *(const float4*)(cb + (size_t)k * NC + c);

    const size_t zbase = ((size_t)b * NC + c) * NHW + hw;
    float zv0 = z[zbase];
    float zv1 = z[zbase + NHW];
    float zv2 = z[zbase + 2 * NHW];
    float zv3 = z[zbase + 3 * NHW];

    out[zbase]           = zv0 + (q.x - zv0);
    out[zbase + NHW]     = zv1 + (q.y - zv1);
    out[zbase + 2 * NHW] = zv2 + (q.z - zv2);
    out[zbase + 3 * NHW] = zv3 + (q.w - zv3);

    if (cq == 0) {
        atomicAdd(&g_counts[k], 1);
        out[NQ + n] = (float)k;
    }

    float dx = zv0 - q.x, dy = zv1 - q.y, dz = zv2 - q.z, dw = zv3 - q.w;
    double s = (double)dx * dx + (double)dy * dy + (double)dz * dz + (double)dw * dw;
#pragma unroll
    for (int off = 16; off; off >>= 1) s += __shfl_down_sync(0xffffffffu, s, off);
    __shared__ double ws[8];
    if ((tid & 31) == 0) ws[tid >> 5] = s;
    __syncthreads();
    if (tid == 0) {
        double t = 0.0;
#pragma unroll
        for (int i = 0; i < 8; i++) t += ws[i];
        atomicAdd(&g_loss, t);
    }
}

// ===================== finalize =====================
__global__ void vq_finalize_kernel(float* __restrict__ out) {
    const int tid = threadIdx.x;
    double s = 0.0;
    for (int k = tid; k < NK; k += 256) {
        int c = g_counts[k];
        if (c > 0) {
            double p = (double)c / (double)NTOK;
            s += p * log(p);
        }
    }
#pragma unroll
    for (int off = 16; off; off >>= 1) s += __shfl_down_sync(0xffffffffu, s, off);
    __shared__ double ws[8];
    if ((tid & 31) == 0) ws[tid >> 5] = s;
    __syncthreads();
    if (tid == 0) {
        double t = 0.0;
#pragma unroll
        for (int i = 0; i < 8; i++) t += ws[i];
        float perp = (float)exp(-t);
        float loss = (float)(g_loss / (double)NQ);
        out[NQ + NTOK + 0] = perp;
        out[NQ + NTOK + 1] = loss;
        out[NQ + NTOK + 2] = loss;
    }
}

// ===================== launch =====================
extern "C" void kernel_launch(void* const* d_in, const int* in_sizes, int n_in,
                              void* d_out, int out_size) {
    const float* z  = (const float*)d_in[0];
    const float* cb = (const float*)d_in[1];
    float* out = (float*)d_out;

    static bool attr_set = false;
    if (!attr_set) {
        cudaFuncSetAttribute(vq_argmin_mma_kernel,
                             cudaFuncAttributeMaxDynamicSharedMemorySize, SM_TOTAL);
        attr_set = true;
    }

    vq_prep_z_kernel<<<dim3(32, 8, 16), 256>>>(z);
    vq_prep_cb_kernel<<<NK / 8, 256>>>(cb);
    vq_argmin_mma_kernel<<<NTOK / 128, 512, SM_TOTAL>>>(cb);
    vq_writeback_kernel<<<NQ / 1024, 256>>>(z, cb, out);
    vq_finalize_kernel<<<1, 256>>>(out);
}

// round 12
// speedup vs baseline: 1.1306x; 1.1306x over previous
#include <cuda_runtime.h>
#include <cuda_bf16.h>
#include <math.h>
#include <stdint.h>

// ===================== problem constants =====================
#define NB   16
#define NC   256
#define NHW  1024
#define NTOK (NB * NHW)        // 16384
#define NK   8192
#define NQ   (NB * NC * NHW)   // 4194304

#define DELTA 0.75f
#define CAND_CAP 16
#define CK_STRIDE 64

// ===================== device scratch =====================
__device__ __align__(16) uint32_t g_zfrag[(NTOK / 128) * 16384];  // 8MB, frag-order A
__device__ __align__(16) __nv_bfloat16 g_ebf[NK * NC];            // 4MB, bf16(-2e)
__device__ __align__(16) float g_zt[NTOK * NC];                   // 16MB, z transposed [n][c]
__device__ float  g_cbnorm[NK];
__device__ __align__(16) int g_idx[NTOK];
__device__ int    g_nc[NTOK];
__device__ int    g_ck[NTOK * CK_STRIDE];
__device__ int    g_counts[NK];
__device__ double g_loss;

__device__ __forceinline__ uint32_t smem_u32(const void* p) {
    uint32_t a;
    asm("{ .reg .u64 t; cvta.to.shared.u64 t, %1; cvt.u32.u64 %0, t; }" : "=r"(a) : "l"(p));
    return a;
}

// ===================== prep z: transpose + staged frag writes + fp32 copy ======
__global__ void vq_prep_z_kernel(const float* __restrict__ z) {
    __shared__ float t[32][33];
    __shared__ uint32_t fr[512];
    int b   = blockIdx.z;
    int hw0 = blockIdx.x * 32;
    int c0  = blockIdx.y * 32;
    int lane = threadIdx.x & 31;
    int gq   = threadIdx.x >> 5;   // 0..7
    const float* zp = z + ((size_t)b * NC + c0) * NHW + hw0;
#pragma unroll
    for (int r = 0; r < 4; r++) {
        int cc = gq * 4 + r;
        t[cc][lane] = zp[(size_t)cc * NHW + lane];
    }
    __syncthreads();
#pragma unroll
    for (int it = 0; it < 2; it++) {
        int slot = threadIdx.x + it * 256;      // 0..511
        int hw_i = slot & 31;
        int cp   = slot >> 5;                   // 0..15
        float v0 = t[2 * cp][hw_i];
        float v1 = t[2 * cp + 1][hw_i];
        uint32_t lo = (uint32_t)__bfloat16_as_ushort(__float2bfloat16(v0));
        uint32_t hi = (uint32_t)__bfloat16_as_ushort(__float2bfloat16(v1));
        uint32_t pk = lo | (hi << 16);

        int kk = (2 * cp) & 15;
        int s  = cp >> 3;                       // ks selector (0/1)
        int u  = hw_i >> 4;                     // mt selector (0/1)
        int g  = hw_i & 7;
        int rl = (hw_i >> 3) & 1;
        int tg = (kk >> 1) & 3;
        int rh = kk >> 3;
        int l  = g * 4 + tg;
        int r  = rl + 2 * rh;
        fr[(s * 2 + u) * 128 + l * 4 + r] = pk;
    }
#pragma unroll
    for (int i = 0; i < 4; i++) {
        int tok_l = gq * 4 + i;
        int n = b * NHW + hw0 + tok_l;
        g_zt[(size_t)n * NC + c0 + lane] = t[lane][tok_l];
    }
    __syncthreads();
    if (threadIdx.x < 128) {
        int q = threadIdx.x;
        int s = q >> 6, u = (q >> 5) & 1, off = q & 31;
        int n0  = b * NHW + hw0;
        int blk = n0 >> 7;
        int mt0 = (n0 & 127) >> 4;
        int ks0 = c0 >> 4;
        uint4* dst4 = (uint4*)g_zfrag;
        const uint4* fr4 = (const uint4*)fr;
        dst4[(size_t)((blk * 16 + ks0 + s) * 8 + (mt0 + u)) * 32 + off] = fr4[q];
    }
}

// ===================== fused prep: cbnorm + bf16(-2e) + init =====================
__global__ void vq_prep_cb_kernel(const float* __restrict__ cb) {
    int row  = blockIdx.x * 8 + (threadIdx.x >> 5);
    int lane = threadIdx.x & 31;
    const float* rp = cb + (size_t)row * NC;
    float v[8];
    float s = 0.f;
#pragma unroll
    for (int i = 0; i < 8; i++) {
        v[i] = rp[lane + i * 32];
        s += v[i] * v[i];
    }
#pragma unroll
    for (int off = 16; off; off >>= 1) s += __shfl_down_sync(0xffffffffu, s, off);
    if (lane == 0) g_cbnorm[row] = s;
#pragma unroll
    for (int i = 0; i < 8; i++)
        g_ebf[(size_t)row * NC + lane + i * 32] = __float2bfloat16(-2.0f * v[i]);
    int gid = blockIdx.x * 256 + threadIdx.x;
    if (gid < NK) g_counts[gid] = 0;
    if (gid == 0) g_loss = 0.0;
}

// ===================== main kernel: R7 body + candidate-distance filter ==========
// SMEM layout (bytes):
//   [0, 65536)         A frags
//   [65536, 102400)    B double buffer: 2 x 128 rows x 144B
//   [102400, 135168)   cbnorm (8192 f32)
//   [135168, 137216)   snc[16][32]
//   [137216, 169984)   scand[16][32][16]  (candidate indices)
//   [169984, 202752)   scandd[16][32][16] (approx distances)
//   [202752, 204800)   sminv[16][32]      (per-warp-token running min)
#define SM_A      0
#define SM_B      65536
#define SM_BSTG   18432
#define BROW_STRIDE 144
#define SM_CBN    102400
#define SM_SNC    135168
#define SM_SCAND  137216
#define SM_SCANDD 169984
#define SM_SMINV  202752
#define SM_TOTAL  204800

__global__ void __launch_bounds__(512, 1) vq_argmin_mma_kernel() {
    extern __shared__ char smem[];
    uint32_t sb = smem_u32(smem);
    const int tid  = threadIdx.x;
    const int wid  = tid >> 5;
    const int lane = tid & 31;
    const int wm   = wid >> 2;       // 0..3
    const int wn   = wid & 3;        // 0..3
    const int g    = lane >> 2;      // 0..7
    const int tg   = lane & 3;       // 0..3
    const int blk  = blockIdx.x;
    const int n_base = blk * 128;

    uint4*  Asm    = (uint4*)(smem + SM_A);
    float*  cbn    = (float*)(smem + SM_CBN);
    int*    snc    = (int*)(smem + SM_SNC);
    int*    scand  = (int*)(smem + SM_SCAND);
    float*  scandd = (float*)(smem + SM_SCANDD);
    float*  sminv  = (float*)(smem + SM_SMINV);

    // ---- stage A frags + cbnorm, zero counters ----
    {
        const uint4* src = (const uint4*)(g_zfrag + (size_t)blk * 16384);
#pragma unroll
        for (int i = 0; i < 8; i++) Asm[tid + i * 512] = src[tid + i * 512];
        const float4* cs = (const float4*)g_cbnorm;
        float4* cd = (float4*)cbn;
#pragma unroll
        for (int i = 0; i < 4; i++) cd[tid + i * 512] = cs[tid + i * 512];
        snc[tid] = 0;
    }
    __syncthreads();

    // ---- cp.async B loader ----
    const int brow = tid >> 2;        // 0..127
    const int bq   = tid & 3;         // 32B quarter
    {
        const char* src = (const char*)(g_ebf) + (size_t)brow * 512 + bq * 32;
        uint32_t dst = sb + SM_B + brow * BROW_STRIDE + bq * 32;
        asm volatile("cp.async.cg.shared.global [%0], [%1], 16;" :: "r"(dst), "l"(src));
        asm volatile("cp.async.cg.shared.global [%0], [%1], 16;" :: "r"(dst + 16), "l"(src + 16));
        asm volatile("cp.async.commit_group;" ::: "memory");
    }

    float acc[2][4][4];
    float minv[4];
#pragma unroll
    for (int i = 0; i < 4; i++) minv[i] = 3.4e38f;

    const int rowsel = lane >> 4;
    const int kbsel  = ((lane >> 3) & 1) * 16;
    const uint32_t bA1 = (uint32_t)(((wn * 4 + rowsel) * 8 + (lane & 7)) * BROW_STRIDE + kbsel);
    const uint32_t bA2 = (uint32_t)(((wn * 4 + 2 + rowsel) * 8 + (lane & 7)) * BROW_STRIDE + kbsel);

    for (int T = 0; T < 256; T++) {
        const int tile = T >> 2;
        const int q2   = T & 3;

        asm volatile("cp.async.wait_group 0;" ::: "memory");
        __syncthreads();

        if (T + 1 < 256) {
            const int Tn = T + 1;
            const char* src = (const char*)(g_ebf) +
                (size_t)((Tn >> 2) * 128 + brow) * 512 + (Tn & 3) * 128 + bq * 32;
            uint32_t dst = sb + SM_B + ((Tn & 1) * SM_BSTG) + brow * BROW_STRIDE + bq * 32;
            asm volatile("cp.async.cg.shared.global [%0], [%1], 16;" :: "r"(dst), "l"(src));
            asm volatile("cp.async.cg.shared.global [%0], [%1], 16;" :: "r"(dst + 16), "l"(src + 16));
            asm volatile("cp.async.commit_group;" ::: "memory");
        }

        if (q2 == 0) {
#pragma unroll
            for (int m = 0; m < 2; m++)
#pragma unroll
                for (int j = 0; j < 4; j++)
#pragma unroll
                    for (int r = 0; r < 4; r++) acc[m][j][r] = 0.f;
        }

        const uint32_t bbase = sb + SM_B + (T & 1) * SM_BSTG;
#pragma unroll
        for (int s2 = 0; s2 < 4; s2++) {
            const int ks = q2 * 4 + s2;
            uint32_t a[2][4];
#pragma unroll
            for (int m2 = 0; m2 < 2; m2++) {
                uint4 v = Asm[(ks * 8 + (wm * 2 + m2)) * 32 + lane];
                a[m2][0] = v.x; a[m2][1] = v.y; a[m2][2] = v.z; a[m2][3] = v.w;
            }
            uint32_t b[4][2];
            asm volatile("ldmatrix.sync.aligned.m8n8.x4.shared.b16 {%0,%1,%2,%3}, [%4];"
                : "=r"(b[0][0]), "=r"(b[0][1]), "=r"(b[1][0]), "=r"(b[1][1])
                : "r"(bbase + bA1 + s2 * 32));
            asm volatile("ldmatrix.sync.aligned.m8n8.x4.shared.b16 {%0,%1,%2,%3}, [%4];"
                : "=r"(b[2][0]), "=r"(b[2][1]), "=r"(b[3][0]), "=r"(b[3][1])
                : "r"(bbase + bA2 + s2 * 32));
#pragma unroll
            for (int m2 = 0; m2 < 2; m2++)
#pragma unroll
                for (int j = 0; j < 4; j++) {
                    asm volatile(
                        "mma.sync.aligned.m16n8k16.row.col.f32.bf16.bf16.f32 "
                        "{%0,%1,%2,%3}, {%4,%5,%6,%7}, {%8,%9}, {%0,%1,%2,%3};"
                        : "+f"(acc[m2][j][0]), "+f"(acc[m2][j][1]),
                          "+f"(acc[m2][j][2]), "+f"(acc[m2][j][3])
                        : "r"(a[m2][0]), "r"(a[m2][1]), "r"(a[m2][2]), "r"(a[m2][3]),
                          "r"(b[j][0]), "r"(b[j][1]));
                }
        }

        if (q2 == 3) {
            const int nb = tile * 128 + wn * 32;
            float2 cb2[4];
#pragma unroll
            for (int j = 0; j < 4; j++)
                cb2[j] = *(const float2*)(cbn + nb + j * 8 + 2 * tg);
#pragma unroll
            for (int mh = 0; mh < 4; mh++) {
                const int m = mh >> 1, h = mh & 1;
                float d0[8];
#pragma unroll
                for (int j = 0; j < 4; j++) {
                    d0[2 * j]     = acc[m][j][2 * h]     + cb2[j].x;
                    d0[2 * j + 1] = acc[m][j][2 * h + 1] + cb2[j].y;
                }
                float lm = d0[0];
#pragma unroll
                for (int i = 1; i < 8; i++) lm = fminf(lm, d0[i]);
                lm = fminf(lm, __shfl_xor_sync(0xffffffffu, lm, 1));
                lm = fminf(lm, __shfl_xor_sync(0xffffffffu, lm, 2));
                if (lm < minv[mh] + DELTA) {
                    const float thr2 = fminf(minv[mh], lm) + DELTA;
                    const int tl = m * 16 + h * 8 + g;
#pragma unroll
                    for (int j = 0; j < 4; j++)
#pragma unroll
                        for (int p = 0; p < 2; p++) {
                            float d = d0[2 * j + p];
                            if (d < thr2) {
                                int slot = atomicAdd(&snc[wid * 32 + tl], 1);
                                if (slot < CAND_CAP) {
                                    scand[(wid * 32 + tl) * CAND_CAP + slot] =
                                        nb + j * 8 + 2 * tg + p;
                                    scandd[(wid * 32 + tl) * CAND_CAP + slot] = d;
                                }
                            }
                        }
                    minv[mh] = fminf(minv[mh], lm);
                }
            }
        }
    }

    // publish per-warp-token running minima (quad-uniform, tg==0 writes)
    if (tg == 0) {
#pragma unroll
        for (int mh = 0; mh < 4; mh++) {
            const int tl = (mh >> 1) * 16 + (mh & 1) * 8 + g;
            sminv[wid * 32 + tl] = minv[mh];
        }
    }
    __syncthreads();

    // -------- merge + FILTER: keep only candidates within gmin + DELTA --------
    if (tid < 128) {
        const int wmg = tid >> 5, tl = tid & 31;
        const int tok = n_base + tid;
        float gmin = 3.4e38f;
#pragma unroll
        for (int j = 0; j < 4; j++)
            gmin = fminf(gmin, sminv[(wmg * 4 + j) * 32 + tl]);
        const float thr = gmin + DELTA;
        int total = 0;
        bool ovf = false;
        for (int j = 0; j < 4; j++) {
            const int w = wmg * 4 + j;
            int cnum = snc[w * 32 + tl];
            if (cnum > CAND_CAP) { ovf = true; cnum = CAND_CAP; }
            for (int s = 0; s < cnum; s++) {
                if (scandd[(w * 32 + tl) * CAND_CAP + s] <= thr) {
                    g_ck[tok * CK_STRIDE + total] = scand[(w * 32 + tl) * CAND_CAP + s];
                    total++;
                }
            }
        }
        g_nc[tok] = ovf ? 255 : total;
    }
}

// ===================== exact rescoring (fast path nc==1) =====================
__device__ __forceinline__ float vq_exact_dist(const float* __restrict__ cb,
                                               const float zr[8], int k, int lane) {
    const float* cr = cb + (size_t)k * NC + lane;
    float s = 0.f;
#pragma unroll
    for (int u = 0; u < 8; u++) s += zr[u] * cr[u * 32];
#pragma unroll
    for (int off = 16; off; off >>= 1) s += __shfl_xor_sync(0xffffffffu, s, off);
    return g_cbnorm[k] - 2.0f * s;
}

__global__ void vq_rescore_kernel(const float* __restrict__ cb) {
    int n = (blockIdx.x * blockDim.x + threadIdx.x) >> 5;
    int lane = threadIdx.x & 31;
    if (n >= NTOK) return;
    int nc = g_nc[n];

    if (nc == 1) {           // sole survivor of the filter is provably the argmin
        if (lane == 0) g_idx[n] = g_ck[n * CK_STRIDE];
        return;
    }

    const float* zp = g_zt + (size_t)n * NC;
    float zr[8];
#pragma unroll
    for (int u = 0; u < 8; u++) zr[u] = zp[lane + u * 32];

    float bd = 3.4e38f;
    int bk = 0x7fffffff;
    if (nc < 255) {
        for (int i = 0; i < nc; i++) {
            int k = g_ck[n * CK_STRIDE + i];
            float d = vq_exact_dist(cb, zr, k, lane);
            if (d < bd || (d == bd && k < bk)) { bd = d; bk = k; }
        }
    } else {
        for (int k = 0; k < NK; k++) {
            float d = vq_exact_dist(cb, zr, k, lane);
            if (d < bd || (d == bd && k < bk)) { bd = d; bk = k; }
        }
    }
    if (lane == 0) g_idx[n] = bk;
}

// ===================== writeback =====================
__global__ void vq_writeback_kernel(const float* __restrict__ z, const float* __restrict__ cb,
                                    float* __restrict__ out) {
    const int tid = threadIdx.x;
    const int gid = blockIdx.x * 256 + tid;
    const int hw  = gid & 1023;
    const int cq  = (gid >> 10) & 63;
    const int b   = gid >> 16;
    const int n   = (b << 10) | hw;
    const int c   = cq * 4;

    const int k = g_idx[n];
    float4 q = *(const float4*)(cb + (size_t)k * NC + c);

    const size_t zbase = ((size_t)b * NC + c) * NHW + hw;
    float zv0 = z[zbase];
    float zv1 = z[zbase + NHW];
    float zv2 = z[zbase + 2 * NHW];
    float zv3 = z[zbase + 3 * NHW];

    out[zbase]           = zv0 + (q.x - zv0);
    out[zbase + NHW]     = zv1 + (q.y - zv1);
    out[zbase + 2 * NHW] = zv2 + (q.z - zv2);
    out[zbase + 3 * NHW] = zv3 + (q.w - zv3);

    if (cq == 0) {
        atomicAdd(&g_counts[k], 1);
        out[NQ + n] = (float)k;
    }

    float dx = zv0 - q.x, dy = zv1 - q.y, dz = zv2 - q.z, dw = zv3 - q.w;
    double s = (double)dx * dx + (double)dy * dy + (double)dz * dz + (double)dw * dw;
#pragma unroll
    for (int off = 16; off; off >>= 1) s += __shfl_down_sync(0xffffffffu, s, off);
    __shared__ double ws[8];
    if ((tid & 31) == 0) ws[tid >> 5] = s;
    __syncthreads();
    if (tid == 0) {
        double t = 0.0;
#pragma unroll
        for (int i = 0; i < 8; i++) t += ws[i];
        atomicAdd(&g_loss, t);
    }
}

// ===================== finalize =====================
__global__ void vq_finalize_kernel(float* __restrict__ out) {
    const int tid = threadIdx.x;
    double s = 0.0;
    for (int k = tid; k < NK; k += 256) {
        int c = g_counts[k];
        if (c > 0) {
            double p = (double)c / (double)NTOK;
            s += p * log(p);
        }
    }
#pragma unroll
    for (int off = 16; off; off >>= 1) s += __shfl_down_sync(0xffffffffu, s, off);
    __shared__ double ws[8];
    if ((tid & 31) == 0) ws[tid >> 5] = s;
    __syncthreads();
    if (tid == 0) {
        double t = 0.0;
#pragma unroll
        for (int i = 0; i < 8; i++) t += ws[i];
        float perp = (float)exp(-t);
        float loss = (float)(g_loss / (double)NQ);
        out[NQ + NTOK + 0] = perp;
        out[NQ + NTOK + 1] = loss;
        out[NQ + NTOK + 2] = loss;
    }
}

// ===================== launch =====================
extern "C" void kernel_launch(void* const* d_in, const int* in_sizes, int n_in,
                              void* d_out, int out_size) {
    const float* z  = (const float*)d_in[0];
    const float* cb = (const float*)d_in[1];
    float* out = (float*)d_out;

    static bool attr_set = false;
    if (!attr_set) {
        cudaFuncSetAttribute(vq_argmin_mma_kernel,
                             cudaFuncAttributeMaxDynamicSharedMemorySize, SM_TOTAL);
        attr_set = true;
    }

    vq_prep_z_kernel<<<dim3(32, 8, 16), 256>>>(z);
    vq_prep_cb_kernel<<<NK / 8, 256>>>(cb);
    vq_argmin_mma_kernel<<<NTOK / 128, 512, SM_TOTAL>>>();
    vq_rescore_kernel<<<NTOK / 8, 256>>>(cb);
    vq_writeback_kernel<<<NQ / 1024, 256>>>(z, cb, out);
    vq_finalize_kernel<<<1, 256>>>(out);
}